// round 4
// baseline (speedup 1.0000x reference)
#include <cuda_runtime.h>

#define N_NODES 100000
#define E_RAW   300000
#define E_TOT   400000   // raw edges + self loops
#define F1      1024     // heads*hid layer 1
#define HEADS   8
#define F2      128

// ---- scratch (global __device__ arrays; ~73 MB total) ----
__device__ float g_xagg[(size_t)N_NODES * 32];  // per-node, per-head weighted x sum (normalized)
__device__ float g_h2[(size_t)N_NODES * F2];    // layer-2 features per node (51 MB)
__device__ float g_as1[N_NODES * HEADS];
__device__ float g_ad1[N_NODES * HEADS];
__device__ float g_as2[N_NODES];
__device__ float g_ad2[N_NODES];
__device__ int   g_head[N_NODES];               // per-dst linked list head
__device__ int   g_next[E_TOT];                 // linked list next
__device__ int   g_src[E_TOT];                  // decoded int32 src per edge
__device__ float g_M1s[4 * HEADS];              // W1^T @ a_src  (4 x 8)
__device__ float g_M1d[4 * HEADS];              // W1^T @ a_dst  (4 x 8)
__device__ int   g_is64;                        // edge_index dtype flag

// ------------------------------------------------------------------
// K-1: detect int64 vs int32 edge_index layout (deterministic).
__global__ void k_detect(const int* __restrict__ ei32) {
    if (threadIdx.x == 0) {
        int any = 0;
        for (int k = 0; k < 256; ++k) any |= ei32[2 * k + 1];
        g_is64 = (any == 0) ? 1 : 0;   // int64 little-endian: high words all zero
    }
}

// K0: init linked-list heads
__global__ void k_init_head() {
    int i = blockIdx.x * blockDim.x + threadIdx.x;
    if (i < N_NODES) g_head[i] = -1;
}

// K1: decode edges + build per-dst linked list (raw + self loops)
__global__ void k_build(const void* __restrict__ ei) {
    int e = blockIdx.x * blockDim.x + threadIdx.x;
    if (e >= E_TOT) return;
    int is64 = g_is64;
    int src, dst;
    if (e < E_RAW) {
        if (is64) {
            src = (int)((const long long*)ei)[e];
            dst = (int)((const long long*)ei)[E_RAW + e];
        } else {
            src = ((const int*)ei)[e];
            dst = ((const int*)ei)[E_RAW + e];
        }
    } else {
        src = dst = e - E_RAW;
    }
    g_src[e] = src;
    g_next[e] = atomicExch(&g_head[dst], e);
}

// ------------------------------------------------------------------
// K2a: M1s[d][h] = sum_c W1[d, h*128+c] * a_src[h, c]   (and M1d with a_dst)
__global__ void k_reduceW(const float* __restrict__ W1,
                          const float* __restrict__ as, const float* __restrict__ ad) {
    int t = threadIdx.x;
    int idx = t & 31;
    int d = idx >> 3, h = idx & 7;
    const float* a = (t < 32) ? as : ad;
    float s = 0.f;
    const float* wrow = W1 + d * F1 + h * 128;
    const float* arow = a + h * 128;
    for (int c = 0; c < 128; ++c) s += wrow[c] * arow[c];
    if (t < 32) g_M1s[d * 8 + h] = s; else g_M1d[d * 8 + h] = s;
}

// K2b: per-node attention scalars: as1[n,h] = sum_d x[n,d] * M1s[d,h]
__global__ __launch_bounds__(256) void k_nodescal(const float* __restrict__ x) {
    int i = blockIdx.x * blockDim.x + threadIdx.x;   // i = n*8 + h
    if (i >= N_NODES * HEADS) return;
    int n = i >> 3, h = i & 7;
    float x0 = x[n * 4 + 0], x1 = x[n * 4 + 1];
    float x2 = x[n * 4 + 2], x3 = x[n * 4 + 3];
    g_as1[i] = x0 * g_M1s[0 * 8 + h] + x1 * g_M1s[1 * 8 + h]
             + x2 * g_M1s[2 * 8 + h] + x3 * g_M1s[3 * 8 + h];
    g_ad1[i] = x0 * g_M1d[0 * 8 + h] + x1 * g_M1d[1 * 8 + h]
             + x2 * g_M1d[2 * 8 + h] + x3 * g_M1d[3 * 8 + h];
}

// ------------------------------------------------------------------
// K3: layer-1 gather in x-space. Warp per dst node.
// lane l: head = l>>2, dim = l&3. acc = sum_e p_e * x[src_e][dim], denom per
// head; writes normalized xagg[i][l] = acc/denom. x is 1.6MB -> L2 resident.
__global__ __launch_bounds__(256) void k_gather1(const float* __restrict__ x) {
    int i = blockIdx.x * 8 + (threadIdx.x >> 5);
    if (i >= N_NODES) return;
    int lane = threadIdx.x & 31;
    int hh = lane >> 2, dd = lane & 3;

    float adst = (lane < 8) ? g_ad1[i * HEADS + lane] : 0.f;
    float acc = 0.f, denom = 0.f;

    int e = (lane == 0) ? g_head[i] : 0;
    for (;;) {
        int ec = __shfl_sync(0xffffffffu, e, 0);
        if (ec < 0) break;
        int src = g_src[ec];
        float pp = 0.f;
        if (lane < 8) {
            float tt = g_as1[src * HEADS + lane] + adst;
            tt = (tt > 0.f) ? tt : 0.2f * tt;        // leaky_relu 0.2
            pp = __expf(tt);
        }
        float p = __shfl_sync(0xffffffffu, pp, hh);
        denom += p;
        acc += p * x[src * 4 + dd];
        if (lane == 0) e = g_next[ec];
    }
    g_xagg[(size_t)i * 32 + lane] = acc / (denom + 1e-16f);
}

// ------------------------------------------------------------------
// K4: fused layer-1 reconstruct + layer-2 GEMM.
// Per block: 32 nodes. Reconstruct a1 = relu(xagg_head @ W1_head + b1)
// chunk-by-chunk (128-k chunk kb == head kb) into smem [k][node], then
// accumulate 4x4 register tiles against W2. Fused att2 dots in epilogue.
__global__ __launch_bounds__(256) void k_fused2(
    const float* __restrict__ W1, const float* __restrict__ b1,
    const float* __restrict__ W2,
    const float* __restrict__ as2, const float* __restrict__ ad2)
{
    __shared__ __align__(16) float sxm[128 * 36];   // [k within chunk][node], pad 36
    __shared__ __align__(16) float s_xa[32][33];    // [node][head*4+d]
    int t = threadIdx.x;
    int ci = t & 31, mi = t >> 5;
    int base = blockIdx.x * 32;

    // load xagg tile: 1024 floats, 256 threads -> 4 each (scalar, conflict-free)
    #pragma unroll
    for (int q = 0; q < 4; ++q) {
        int idx = t * 4 + q;             // node = idx>>5, col = idx&31
        s_xa[idx >> 5][idx & 31] = g_xagg[(size_t)(base + (idx >> 5)) * 32 + (idx & 31)];
    }
    __syncthreads();

    float4 acc[4];
    #pragma unroll
    for (int j = 0; j < 4; ++j) acc[j] = make_float4(0.f, 0.f, 0.f, 0.f);

    int ln = t >> 3;       // producer: node 0..31
    int kq = t & 7;        // producer: 16-float chunk within 128-k slab

    for (int kb = 0; kb < 8; ++kb) {
        // reconstruct relu(xagg_head @ W1 + b1) for this head's 128 channels
        float xa0 = s_xa[ln][kb * 4 + 0], xa1 = s_xa[ln][kb * 4 + 1];
        float xa2 = s_xa[ln][kb * 4 + 2], xa3 = s_xa[ln][kb * 4 + 3];
        #pragma unroll
        for (int q = 0; q < 4; ++q) {
            int kk = kq * 16 + q * 4;
            int c = kb * 128 + kk;
            float4 w0 = *(const float4*)(W1 + 0 * F1 + c);
            float4 w1 = *(const float4*)(W1 + 1 * F1 + c);
            float4 w2 = *(const float4*)(W1 + 2 * F1 + c);
            float4 w3 = *(const float4*)(W1 + 3 * F1 + c);
            float4 bb = *(const float4*)(b1 + c);
            float4 v;
            v.x = fmaxf(xa0 * w0.x + xa1 * w1.x + xa2 * w2.x + xa3 * w3.x + bb.x, 0.f);
            v.y = fmaxf(xa0 * w0.y + xa1 * w1.y + xa2 * w2.y + xa3 * w3.y + bb.y, 0.f);
            v.z = fmaxf(xa0 * w0.z + xa1 * w1.z + xa2 * w2.z + xa3 * w3.z + bb.z, 0.f);
            v.w = fmaxf(xa0 * w0.w + xa1 * w1.w + xa2 * w2.w + xa3 * w3.w + bb.w, 0.f);
            sxm[(kk + 0) * 36 + ln] = v.x;
            sxm[(kk + 1) * 36 + ln] = v.y;
            sxm[(kk + 2) * 36 + ln] = v.z;
            sxm[(kk + 3) * 36 + ln] = v.w;
        }
        __syncthreads();
        #pragma unroll 8
        for (int k = 0; k < 128; ++k) {
            float4 xv = *(const float4*)(&sxm[k * 36 + 4 * mi]);
            float4 wv = *(const float4*)(W2 + (size_t)(kb * 128 + k) * F2 + 4 * ci);
            acc[0].x += xv.x * wv.x; acc[0].y += xv.x * wv.y; acc[0].z += xv.x * wv.z; acc[0].w += xv.x * wv.w;
            acc[1].x += xv.y * wv.x; acc[1].y += xv.y * wv.y; acc[1].z += xv.y * wv.z; acc[1].w += xv.y * wv.w;
            acc[2].x += xv.z * wv.x; acc[2].y += xv.z * wv.y; acc[2].z += xv.z * wv.z; acc[2].w += xv.z * wv.w;
            acc[3].x += xv.w * wv.x; acc[3].y += xv.w * wv.y; acc[3].z += xv.w * wv.z; acc[3].w += xv.w * wv.w;
        }
        __syncthreads();
    }

    // epilogue: store h2 tile + fused attention dots (warp == fixed mi, lanes == ci)
    float4 asv = *((const float4*)as2 + ci);
    float4 adv = *((const float4*)ad2 + ci);
    #pragma unroll
    for (int j = 0; j < 4; ++j) {
        int node = base + 4 * mi + j;
        ((float4*)(g_h2 + (size_t)node * F2))[ci] = acc[j];
        float ss = acc[j].x * asv.x + acc[j].y * asv.y + acc[j].z * asv.z + acc[j].w * asv.w;
        float sd = acc[j].x * adv.x + acc[j].y * adv.y + acc[j].z * adv.z + acc[j].w * adv.w;
        #pragma unroll
        for (int o = 16; o; o >>= 1) {
            ss += __shfl_xor_sync(0xffffffffu, ss, o);
            sd += __shfl_xor_sync(0xffffffffu, sd, o);
        }
        if (ci == 0) { g_as2[node] = ss; g_ad2[node] = sd; }
    }
}

// ------------------------------------------------------------------
// K5: layer-2 gather (single head). Warp per node; lane owns one float4
// (128 channels = 32 lanes x 4). Fused bias + relu, writes d_out directly.
__global__ __launch_bounds__(256) void k_gather2(
    const float* __restrict__ b2, float* __restrict__ out)
{
    int i = blockIdx.x * 8 + (threadIdx.x >> 5);
    if (i >= N_NODES) return;
    int lane = threadIdx.x & 31;

    float adst = g_ad2[i];
    float denom = 0.f;
    float4 acc = make_float4(0.f, 0.f, 0.f, 0.f);

    int e = (lane == 0) ? g_head[i] : 0;
    for (;;) {
        int ec = __shfl_sync(0xffffffffu, e, 0);
        if (ec < 0) break;
        int src = g_src[ec];
        float tt = g_as2[src] + adst;   // broadcast load
        tt = (tt > 0.f) ? tt : 0.2f * tt;
        float p = __expf(tt);
        denom += p;
        float4 v = ((const float4*)(g_h2 + (size_t)src * F2))[lane];
        acc.x += p * v.x; acc.y += p * v.y; acc.z += p * v.z; acc.w += p * v.w;
        if (lane == 0) e = g_next[ec];
    }

    float inv = 1.f / (denom + 1e-16f);
    float4 bb = *((const float4*)b2 + lane);
    float4 r;
    r.x = fmaxf(acc.x * inv + bb.x, 0.f);
    r.y = fmaxf(acc.y * inv + bb.y, 0.f);
    r.z = fmaxf(acc.z * inv + bb.z, 0.f);
    r.w = fmaxf(acc.w * inv + bb.w, 0.f);
    ((float4*)(out + (size_t)i * F2))[lane] = r;
}

// ------------------------------------------------------------------
extern "C" void kernel_launch(void* const* d_in, const int* in_sizes, int n_in,
                              void* d_out, int out_size)
{
    const float* x   = (const float*)d_in[0];
    const void*  ei  = d_in[1];                 // [2, 300000] (int64 expected)
    const float* W1  = (const float*)d_in[2];
    const float* as1 = (const float*)d_in[3];
    const float* ad1 = (const float*)d_in[4];
    const float* b1  = (const float*)d_in[5];
    const float* W2  = (const float*)d_in[6];
    const float* as2 = (const float*)d_in[7];
    const float* ad2 = (const float*)d_in[8];
    const float* b2  = (const float*)d_in[9];
    float* out = (float*)d_out;

    k_detect<<<1, 32>>>((const int*)ei);
    k_init_head<<<(N_NODES + 255) / 256, 256>>>();
    k_build<<<(E_TOT + 255) / 256, 256>>>(ei);
    k_reduceW<<<1, 64>>>(W1, as1, ad1);
    k_nodescal<<<(N_NODES * HEADS + 255) / 256, 256>>>(x);
    k_gather1<<<(N_NODES + 7) / 8, 256>>>(x);
    k_fused2<<<N_NODES / 32, 256>>>(W1, b1, W2, as2, ad2);
    k_gather2<<<(N_NODES + 7) / 8, 256>>>(b2, out);
}

// round 5
// speedup vs baseline: 3.1861x; 3.1861x over previous
#include <cuda_runtime.h>
#include <cstdint>

#define N_NODES 100000
#define E_RAW   300000
#define E_TOT   400000   // raw edges + self loops
#define F1      1024     // heads*hid layer 1
#define HEADS   8
#define F2      128
#define M_TILE  64
#define KC      32       // k chunk for fused GEMM

// ---- scratch (global __device__ arrays; ~73 MB total) ----
__device__ float g_xagg[(size_t)N_NODES * 32];  // per-node, per-head weighted x sum (normalized)
__device__ float g_h2[(size_t)N_NODES * F2];    // layer-2 features per node (51 MB)
__device__ float g_as1[N_NODES * HEADS];
__device__ float g_ad1[N_NODES * HEADS];
__device__ float g_as2[N_NODES];
__device__ float g_ad2[N_NODES];
__device__ int   g_head[N_NODES];               // per-dst linked list head
__device__ int   g_next[E_TOT];                 // linked list next
__device__ int   g_src[E_TOT];                  // decoded int32 src per edge
__device__ float g_M1s[4 * HEADS];              // W1^T @ a_src  (4 x 8)
__device__ float g_M1d[4 * HEADS];              // W1^T @ a_dst  (4 x 8)
__device__ int   g_is64;                        // edge_index dtype flag

__device__ __forceinline__ uint32_t f2tf(float f) {
    uint32_t u;
    asm("cvt.rna.tf32.f32 %0, %1;" : "=r"(u) : "f"(f));
    return u;
}

#define MMA_TF32(d, a, b) \
    asm volatile("mma.sync.aligned.m16n8k8.row.col.f32.tf32.tf32.f32 " \
        "{%0,%1,%2,%3}, {%4,%5,%6,%7}, {%8,%9}, {%0,%1,%2,%3};" \
        : "+f"((d)[0]), "+f"((d)[1]), "+f"((d)[2]), "+f"((d)[3]) \
        : "r"((a)[0]), "r"((a)[1]), "r"((a)[2]), "r"((a)[3]), \
          "r"((b)[0]), "r"((b)[1]))

// ------------------------------------------------------------------
// K-1: detect int64 vs int32 edge_index layout (deterministic).
__global__ void k_detect(const int* __restrict__ ei32) {
    if (threadIdx.x == 0) {
        int any = 0;
        for (int k = 0; k < 256; ++k) any |= ei32[2 * k + 1];
        g_is64 = (any == 0) ? 1 : 0;   // int64 little-endian: high words all zero
    }
}

// K0: init linked-list heads
__global__ void k_init_head() {
    int i = blockIdx.x * blockDim.x + threadIdx.x;
    if (i < N_NODES) g_head[i] = -1;
}

// K1: decode edges + build per-dst linked list (raw + self loops)
__global__ void k_build(const void* __restrict__ ei) {
    int e = blockIdx.x * blockDim.x + threadIdx.x;
    if (e >= E_TOT) return;
    int is64 = g_is64;
    int src, dst;
    if (e < E_RAW) {
        if (is64) {
            src = (int)((const long long*)ei)[e];
            dst = (int)((const long long*)ei)[E_RAW + e];
        } else {
            src = ((const int*)ei)[e];
            dst = ((const int*)ei)[E_RAW + e];
        }
    } else {
        src = dst = e - E_RAW;
    }
    g_src[e] = src;
    g_next[e] = atomicExch(&g_head[dst], e);
}

// ------------------------------------------------------------------
// K2a: M1s[d][h] = sum_c W1[d, h*128+c] * a_src[h, c]   (and M1d with a_dst)
// 64 outputs x 2 matrices -> 64 warps; 8 blocks x 256 threads.
__global__ void k_reduceW(const float* __restrict__ W1,
                          const float* __restrict__ as, const float* __restrict__ ad) {
    int wid = (blockIdx.x * blockDim.x + threadIdx.x) >> 5;  // 0..63
    int lane = threadIdx.x & 31;
    int idx = wid & 31;
    int d = idx >> 3, h = idx & 7;
    const float* a = (wid < 32) ? as : ad;
    const float* wrow = W1 + d * F1 + h * 128;
    const float* arow = a + h * 128;
    float s = 0.f;
    #pragma unroll
    for (int c = 0; c < 4; ++c) s += wrow[lane + 32 * c] * arow[lane + 32 * c];
    #pragma unroll
    for (int o = 16; o; o >>= 1) s += __shfl_xor_sync(0xffffffffu, s, o);
    if (lane == 0) {
        if (wid < 32) g_M1s[d * 8 + h] = s; else g_M1d[d * 8 + h] = s;
    }
}

// K2b: per-node attention scalars: as1[n,h] = sum_d x[n,d] * M1s[d,h]
__global__ __launch_bounds__(256) void k_nodescal(const float* __restrict__ x) {
    int i = blockIdx.x * blockDim.x + threadIdx.x;   // i = n*8 + h
    if (i >= N_NODES * HEADS) return;
    int n = i >> 3, h = i & 7;
    float x0 = x[n * 4 + 0], x1 = x[n * 4 + 1];
    float x2 = x[n * 4 + 2], x3 = x[n * 4 + 3];
    g_as1[i] = x0 * g_M1s[0 * 8 + h] + x1 * g_M1s[1 * 8 + h]
             + x2 * g_M1s[2 * 8 + h] + x3 * g_M1s[3 * 8 + h];
    g_ad1[i] = x0 * g_M1d[0 * 8 + h] + x1 * g_M1d[1 * 8 + h]
             + x2 * g_M1d[2 * 8 + h] + x3 * g_M1d[3 * 8 + h];
}

// ------------------------------------------------------------------
// K3: layer-1 gather in x-space. Warp per dst node. (x, as1 L2-resident)
__global__ __launch_bounds__(256) void k_gather1(const float* __restrict__ x) {
    int i = blockIdx.x * 8 + (threadIdx.x >> 5);
    if (i >= N_NODES) return;
    int lane = threadIdx.x & 31;
    int hh = lane >> 2, dd = lane & 3;

    float adst = (lane < 8) ? g_ad1[i * HEADS + lane] : 0.f;
    float acc = 0.f, denom = 0.f;

    int e = (lane == 0) ? g_head[i] : 0;
    for (;;) {
        int ec = __shfl_sync(0xffffffffu, e, 0);
        if (ec < 0) break;
        int src = g_src[ec];
        float pp = 0.f;
        if (lane < 8) {
            float tt = g_as1[src * HEADS + lane] + adst;
            tt = (tt > 0.f) ? tt : 0.2f * tt;        // leaky_relu 0.2
            pp = __expf(tt);
        }
        float p = __shfl_sync(0xffffffffu, pp, hh);
        denom += p;
        acc += p * x[src * 4 + dd];
        if (lane == 0) e = g_next[ec];
    }
    g_xagg[(size_t)i * 32 + lane] = acc / (denom + 1e-16f);
}

// ------------------------------------------------------------------
// K4: fused layer-1 reconstruct + layer-2 GEMM on tf32 tensor cores.
// 256 thr / 8 warps; M-tile 64 nodes, N=128, K chunked by 32.
// warp w: mw = w&1 (32 rows), nw = w>>2? no: nw = w>>1 (32 cols).
__global__ __launch_bounds__(256) void k_fused3(
    const float* __restrict__ W1, const float* __restrict__ b1,
    const float* __restrict__ W2,
    const float* __restrict__ as2, const float* __restrict__ ad2)
{
    __shared__ __align__(16) float sA[M_TILE * 36];   // [m][k] pad 36, tf32 bits
    __shared__ __align__(16) float sB[KC * 136];      // [k][n] pad 136, tf32 bits
    __shared__ __align__(16) float sxa[M_TILE * 33];  // [m][32] pad 33
    __shared__ float sred[2 * M_TILE];

    int t = threadIdx.x;
    int base = blockIdx.x * M_TILE;
    int lane = t & 31, w = t >> 5;
    int mw = w & 1, nw = w >> 1;
    int g = lane >> 2, t4 = lane & 3;

    // load xagg tile (guard tail block)
    #pragma unroll
    for (int q = 0; q < 8; ++q) {
        int idx = q * 256 + t;            // 0..2047
        int m = idx >> 5, col = idx & 31;
        float v = (base + m < N_NODES) ? g_xagg[(size_t)(base + m) * 32 + col] : 0.f;
        sxa[m * 33 + col] = v;
    }
    if (t < 2 * M_TILE) sred[t] = 0.f;
    __syncthreads();

    float acc[2][4][4];
    #pragma unroll
    for (int mf = 0; mf < 2; ++mf)
        #pragma unroll
        for (int nf = 0; nf < 4; ++nf)
            #pragma unroll
            for (int q = 0; q < 4; ++q) acc[mf][nf][q] = 0.f;

    int mp = t >> 2;       // producer node 0..63
    int kq = t & 3;        // producer 8-k chunk

    for (int c = 0; c < F1 / KC; ++c) {          // 32 chunks
        int h = c >> 2;
        int kg = c * KC;
        // ---- reconstruct A chunk: relu(xagg_h @ W1 + b1), store tf32 ----
        float xa0 = sxa[mp * 33 + h * 4 + 0], xa1 = sxa[mp * 33 + h * 4 + 1];
        float xa2 = sxa[mp * 33 + h * 4 + 2], xa3 = sxa[mp * 33 + h * 4 + 3];
        #pragma unroll
        for (int j2 = 0; j2 < 2; ++j2) {
            int kk = kq * 8 + j2 * 4;
            int cg = kg + kk;
            float4 w0 = *(const float4*)(W1 + 0 * F1 + cg);
            float4 w1 = *(const float4*)(W1 + 1 * F1 + cg);
            float4 w2 = *(const float4*)(W1 + 2 * F1 + cg);
            float4 w3 = *(const float4*)(W1 + 3 * F1 + cg);
            float4 bb = *(const float4*)(b1 + cg);
            uint4 v;
            v.x = f2tf(fmaxf(xa0 * w0.x + xa1 * w1.x + xa2 * w2.x + xa3 * w3.x + bb.x, 0.f));
            v.y = f2tf(fmaxf(xa0 * w0.y + xa1 * w1.y + xa2 * w2.y + xa3 * w3.y + bb.y, 0.f));
            v.z = f2tf(fmaxf(xa0 * w0.z + xa1 * w1.z + xa2 * w2.z + xa3 * w3.z + bb.z, 0.f));
            v.w = f2tf(fmaxf(xa0 * w0.w + xa1 * w1.w + xa2 * w2.w + xa3 * w3.w + bb.w, 0.f));
            *(uint4*)(&sA[mp * 36 + kk]) = v;
        }
        // ---- stage W2 chunk as tf32 ----
        #pragma unroll
        for (int q = 0; q < 4; ++q) {
            int lin = q * 256 + t;               // 0..1023 float4 units
            int r = lin >> 5, c4 = lin & 31;
            float4 wv = *(const float4*)(W2 + (size_t)(kg + r) * F2 + c4 * 4);
            uint4 u;
            u.x = f2tf(wv.x); u.y = f2tf(wv.y); u.z = f2tf(wv.z); u.w = f2tf(wv.w);
            *(uint4*)(&sB[r * 136 + c4 * 4]) = u;
        }
        __syncthreads();
        // ---- MMA: 4 k-steps of 8 ----
        #pragma unroll
        for (int ks = 0; ks < 4; ++ks) {
            int kc0 = ks * 8;
            uint32_t a[2][4], b[4][2];
            #pragma unroll
            for (int mf = 0; mf < 2; ++mf) {
                const uint32_t* pa = (const uint32_t*)sA + (mw * 32 + mf * 16 + g) * 36 + kc0 + t4;
                a[mf][0] = pa[0];
                a[mf][1] = pa[8 * 36];
                a[mf][2] = pa[4];
                a[mf][3] = pa[8 * 36 + 4];
            }
            #pragma unroll
            for (int nf = 0; nf < 4; ++nf) {
                const uint32_t* pb = (const uint32_t*)sB + (kc0 + t4) * 136 + nw * 32 + nf * 8 + g;
                b[nf][0] = pb[0];
                b[nf][1] = pb[4 * 136];
            }
            #pragma unroll
            for (int mf = 0; mf < 2; ++mf)
                #pragma unroll
                for (int nf = 0; nf < 4; ++nf)
                    MMA_TF32(acc[mf][nf], a[mf], b[nf]);
        }
        __syncthreads();
    }

    // ---- epilogue: store h2 + fused att2 dots ----
    #pragma unroll
    for (int mf = 0; mf < 2; ++mf) {
        #pragma unroll
        for (int half = 0; half < 2; ++half) {
            int mloc = mw * 32 + mf * 16 + g + half * 8;
            int node = base + mloc;
            float ps = 0.f, pd = 0.f;
            #pragma unroll
            for (int nf = 0; nf < 4; ++nf) {
                int col = nw * 32 + nf * 8 + 2 * t4;
                float c0 = acc[mf][nf][half * 2 + 0];
                float c1 = acc[mf][nf][half * 2 + 1];
                if (node < N_NODES) {
                    float2 st; st.x = c0; st.y = c1;
                    *(float2*)(g_h2 + (size_t)node * F2 + col) = st;
                }
                ps += c0 * as2[col] + c1 * as2[col + 1];
                pd += c0 * ad2[col] + c1 * ad2[col + 1];
            }
            ps += __shfl_xor_sync(0xffffffffu, ps, 1);
            ps += __shfl_xor_sync(0xffffffffu, ps, 2);
            pd += __shfl_xor_sync(0xffffffffu, pd, 1);
            pd += __shfl_xor_sync(0xffffffffu, pd, 2);
            if (t4 == 0) {
                atomicAdd(&sred[mloc], ps);
                atomicAdd(&sred[M_TILE + mloc], pd);
            }
        }
    }
    __syncthreads();
    if (t < M_TILE) {
        int node = base + t;
        if (node < N_NODES) {
            g_as2[node] = sred[t];
            g_ad2[node] = sred[M_TILE + t];
        }
    }
}

// ------------------------------------------------------------------
// K5: layer-2 gather (single head). Warp per node. Fused bias+relu -> d_out.
__global__ __launch_bounds__(256) void k_gather2(
    const float* __restrict__ b2, float* __restrict__ out)
{
    int i = blockIdx.x * 8 + (threadIdx.x >> 5);
    if (i >= N_NODES) return;
    int lane = threadIdx.x & 31;

    float adst = g_ad2[i];
    float denom = 0.f;
    float4 acc = make_float4(0.f, 0.f, 0.f, 0.f);

    int e = (lane == 0) ? g_head[i] : 0;
    for (;;) {
        int ec = __shfl_sync(0xffffffffu, e, 0);
        if (ec < 0) break;
        int src = g_src[ec];
        float tt = g_as2[src] + adst;
        tt = (tt > 0.f) ? tt : 0.2f * tt;
        float p = __expf(tt);
        denom += p;
        float4 v = ((const float4*)(g_h2 + (size_t)src * F2))[lane];
        acc.x += p * v.x; acc.y += p * v.y; acc.z += p * v.z; acc.w += p * v.w;
        if (lane == 0) e = g_next[ec];
    }

    float inv = 1.f / (denom + 1e-16f);
    float4 bb = *((const float4*)b2 + lane);
    float4 r;
    r.x = fmaxf(acc.x * inv + bb.x, 0.f);
    r.y = fmaxf(acc.y * inv + bb.y, 0.f);
    r.z = fmaxf(acc.z * inv + bb.z, 0.f);
    r.w = fmaxf(acc.w * inv + bb.w, 0.f);
    ((float4*)(out + (size_t)i * F2))[lane] = r;
}

// ------------------------------------------------------------------
extern "C" void kernel_launch(void* const* d_in, const int* in_sizes, int n_in,
                              void* d_out, int out_size)
{
    const float* x   = (const float*)d_in[0];
    const void*  ei  = d_in[1];                 // [2, 300000] (int64 expected)
    const float* W1  = (const float*)d_in[2];
    const float* as1 = (const float*)d_in[3];
    const float* ad1 = (const float*)d_in[4];
    const float* b1  = (const float*)d_in[5];
    const float* W2  = (const float*)d_in[6];
    const float* as2 = (const float*)d_in[7];
    const float* ad2 = (const float*)d_in[8];
    const float* b2  = (const float*)d_in[9];
    float* out = (float*)d_out;

    k_detect<<<1, 32>>>((const int*)ei);
    k_init_head<<<(N_NODES + 255) / 256, 256>>>();
    k_build<<<(E_TOT + 255) / 256, 256>>>(ei);
    k_reduceW<<<8, 256>>>(W1, as1, ad1);
    k_nodescal<<<(N_NODES * HEADS + 255) / 256, 256>>>(x);
    k_gather1<<<(N_NODES + 7) / 8, 256>>>(x);
    k_fused3<<<(N_NODES + M_TILE - 1) / M_TILE, 256>>>(W1, b1, W2, as2, ad2);
    k_gather2<<<(N_NODES + 7) / 8, 256>>>(b2, out);
}